// round 2
// baseline (speedup 1.0000x reference)
#include <cuda_runtime.h>
#include <math.h>

// Problem constants (fixed by reference setup_inputs)
#define BB 4
#define NN 4096
#define MM 1024
#define QD 320
#define CD 768
#define ID 512
#define HEADS 8
#define DH 64
#define ATT_SCALE 0.125f  // 64^-0.5

// Scratch (static device globals -- allocation-free per harness rules)
__device__ float g_Q[(size_t)BB * NN * ID];  // 33.5 MB
__device__ float g_K[(size_t)BB * MM * ID];  //  8.4 MB
__device__ float g_V[(size_t)BB * MM * ID];  //  8.4 MB
__device__ float g_O[(size_t)BB * NN * ID];  // 33.5 MB

// ---------------------------------------------------------------------------
// Tiled fp32 GEMM: C[M,N] = A[M,K] @ B[K,N] (+ bias)
// BM=128, BN=64, BK=8, 256 threads, 8x4 per-thread register tile.
// Requires: M % 128 == 0, N % 64 == 0, K % 8 == 0 (true for all our shapes).
// ---------------------------------------------------------------------------
__global__ void __launch_bounds__(256) gemm128x64(
    const float* __restrict__ A, const float* __restrict__ Bw,
    float* __restrict__ C, const float* __restrict__ bias,
    int Mdim, int Ndim, int Kdim)
{
    __shared__ float As[8][128];
    __shared__ float Bs[8][64];

    const int tid = threadIdx.x;
    const int tr = tid >> 4;        // 0..15
    const int tc = tid & 15;        // 0..15
    const int m0 = blockIdx.x * 128;
    const int n0 = blockIdx.y * 64;

    // global->smem load mapping
    const int a_row  = tid >> 1;        // 0..127
    const int a_col4 = (tid & 1) * 4;   // 0 or 4
    const int b_row  = tid >> 5;        // 0..7
    const int b_col2 = (tid & 31) * 2;  // 0..62

    float acc[8][4];
#pragma unroll
    for (int i = 0; i < 8; i++)
#pragma unroll
        for (int j = 0; j < 4; j++) acc[i][j] = 0.f;

    for (int k0 = 0; k0 < Kdim; k0 += 8) {
        float4 a4 = *(const float4*)&A[(size_t)(m0 + a_row) * Kdim + k0 + a_col4];
        As[a_col4 + 0][a_row] = a4.x;
        As[a_col4 + 1][a_row] = a4.y;
        As[a_col4 + 2][a_row] = a4.z;
        As[a_col4 + 3][a_row] = a4.w;
        float2 b2 = *(const float2*)&Bw[(size_t)(k0 + b_row) * Ndim + n0 + b_col2];
        Bs[b_row][b_col2 + 0] = b2.x;
        Bs[b_row][b_col2 + 1] = b2.y;
        __syncthreads();

#pragma unroll
        for (int k = 0; k < 8; k++) {
            float a[8], b[4];
#pragma unroll
            for (int i = 0; i < 8; i++) a[i] = As[k][tr * 8 + i];
#pragma unroll
            for (int j = 0; j < 4; j++) b[j] = Bs[k][tc * 4 + j];
#pragma unroll
            for (int i = 0; i < 8; i++)
#pragma unroll
                for (int j = 0; j < 4; j++) acc[i][j] += a[i] * b[j];
        }
        __syncthreads();
    }

#pragma unroll
    for (int i = 0; i < 8; i++) {
        const int m = m0 + tr * 8 + i;
#pragma unroll
        for (int j = 0; j < 4; j++) {
            const int n = n0 + tc * 4 + j;
            float v = acc[i][j];
            if (bias) v += bias[n];
            C[(size_t)m * Ndim + n] = v;
        }
    }
}

// ---------------------------------------------------------------------------
// Flash-style attention: warp-per-query, 2 head-dims per lane.
// grid: x = NN/8 query groups, y = BB*HEADS. 256 threads (8 warps).
// K/V streamed through smem in 64-key tiles; online softmax.
// ---------------------------------------------------------------------------
__global__ void __launch_bounds__(256) attn_kernel(
    const float* __restrict__ Q, const float* __restrict__ K,
    const float* __restrict__ V, float* __restrict__ O)
{
    __shared__ float Ks[64][64];
    __shared__ float Vs[64][64];

    const int bh = blockIdx.y;
    const int b = bh / HEADS;
    const int h = bh % HEADS;
    const int warp = threadIdx.x >> 5;
    const int lane = threadIdx.x & 31;
    const int q = blockIdx.x * 8 + warp;

    const float* qp = &Q[(size_t)(b * NN + q) * ID + h * DH + lane * 2];
    const float q0 = qp[0] * ATT_SCALE;
    const float q1 = qp[1] * ATT_SCALE;

    float m = -INFINITY, l = 0.f, o0 = 0.f, o1 = 0.f;

    for (int j0 = 0; j0 < MM; j0 += 64) {
        // cooperative load of 64x64 K and V head-slices (float4, coalesced)
        for (int t = threadIdx.x; t < 64 * 16; t += 256) {
            const int row = t >> 4;
            const int c4 = (t & 15) * 4;
            const size_t base = (size_t)(b * MM + j0 + row) * ID + h * DH + c4;
            float4 kv = *(const float4*)&K[base];
            Ks[row][c4 + 0] = kv.x; Ks[row][c4 + 1] = kv.y;
            Ks[row][c4 + 2] = kv.z; Ks[row][c4 + 3] = kv.w;
            float4 vv = *(const float4*)&V[base];
            Vs[row][c4 + 0] = vv.x; Vs[row][c4 + 1] = vv.y;
            Vs[row][c4 + 2] = vv.z; Vs[row][c4 + 3] = vv.w;
        }
        __syncthreads();

#pragma unroll 4
        for (int j = 0; j < 64; j++) {
            float s = q0 * Ks[j][lane * 2] + q1 * Ks[j][lane * 2 + 1];
            s += __shfl_xor_sync(0xffffffffu, s, 16);
            s += __shfl_xor_sync(0xffffffffu, s, 8);
            s += __shfl_xor_sync(0xffffffffu, s, 4);
            s += __shfl_xor_sync(0xffffffffu, s, 2);
            s += __shfl_xor_sync(0xffffffffu, s, 1);
            const float mn = fmaxf(m, s);
            const float alpha = __expf(m - mn);   // 0 when m == -inf
            const float p = __expf(s - mn);
            l = l * alpha + p;
            o0 = o0 * alpha + p * Vs[j][lane * 2];
            o1 = o1 * alpha + p * Vs[j][lane * 2 + 1];
            m = mn;
        }
        __syncthreads();
    }

    const float inv = 1.f / l;
    float* op = &O[(size_t)(b * NN + q) * ID + h * DH + lane * 2];
    op[0] = o0 * inv;
    op[1] = o1 * inv;
}

// ---------------------------------------------------------------------------
// Launch: x, context, Wq, Wk, Wv, Wo, bo  ->  out [B, N, QD] fp32
// ---------------------------------------------------------------------------
extern "C" void kernel_launch(void* const* d_in, const int* in_sizes, int n_in,
                              void* d_out, int out_size)
{
    (void)in_sizes; (void)n_in; (void)out_size;
    const float* x   = (const float*)d_in[0];
    const float* ctx = (const float*)d_in[1];
    const float* Wq  = (const float*)d_in[2];
    const float* Wk  = (const float*)d_in[3];
    const float* Wv  = (const float*)d_in[4];
    const float* Wo  = (const float*)d_in[5];
    const float* bo  = (const float*)d_in[6];
    float* out = (float*)d_out;

    float *qb, *kb, *vb, *ob;
    cudaGetSymbolAddress((void**)&qb, g_Q);
    cudaGetSymbolAddress((void**)&kb, g_K);
    cudaGetSymbolAddress((void**)&vb, g_V);
    cudaGetSymbolAddress((void**)&ob, g_O);

    // Q = x @ Wq        : [16384,320] @ [320,512]
    gemm128x64<<<dim3(BB * NN / 128, ID / 64), 256>>>(x, Wq, qb, nullptr,
                                                      BB * NN, ID, QD);
    // K = ctx @ Wk      : [4096,768] @ [768,512]
    gemm128x64<<<dim3(BB * MM / 128, ID / 64), 256>>>(ctx, Wk, kb, nullptr,
                                                      BB * MM, ID, CD);
    // V = ctx @ Wv
    gemm128x64<<<dim3(BB * MM / 128, ID / 64), 256>>>(ctx, Wv, vb, nullptr,
                                                      BB * MM, ID, CD);
    // attention -> g_O  (b, n, h*d layout)
    attn_kernel<<<dim3(NN / 8, BB * HEADS), 256>>>(qb, kb, vb, ob);
    // out = g_O @ Wo + bo : [16384,512] @ [512,320]
    gemm128x64<<<dim3(BB * NN / 128, QD / 64), 256>>>(ob, Wo, out, bo,
                                                      BB * NN, QD, ID);
}

// round 7
// speedup vs baseline: 3.1371x; 3.1371x over previous
#include <cuda_runtime.h>
#include <math.h>

// Problem constants (fixed by reference setup_inputs)
#define BB 4
#define NN 4096
#define MM 1024
#define QD 320
#define CD 768
#define ID 512
#define HEADS 8
#define DH 64
#define ATT_SCALE 0.125f  // 64^-0.5

// Scratch (static device globals -- allocation-free per harness rules)
__device__ float g_Q[(size_t)BB * NN * ID];  // 33.5 MB
__device__ float g_K[(size_t)BB * MM * ID];  //  8.4 MB
__device__ float g_V[(size_t)BB * MM * ID];  //  8.4 MB
__device__ float g_O[(size_t)BB * NN * ID];  // 33.5 MB

// ---------------------------------------------------------------------------
// Tiled fp32 GEMM: C[M,N] = A[M,K] @ B[K,N] (+ bias)
// BM=128, BK=8, 256 threads, thread grid 16x16.
// BN=128: per-thread 8x8 acc (rows/cols split 4+4 at offset 64).
// BN=64 : per-thread 8x4 acc.
// Requires: M % 128 == 0, N % BN == 0, K % 8 == 0.
// ---------------------------------------------------------------------------
template <int BN, int TN>
__global__ void __launch_bounds__(256) gemm_tile(
    const float* __restrict__ A, const float* __restrict__ Bw,
    float* __restrict__ C, const float* __restrict__ bias,
    int Ndim, int Kdim)
{
    __shared__ float As[8][132];       // [k][m], padded (conflict-free stores)
    __shared__ float Bs[8][BN + 4];    // [k][n]

    const int tid = threadIdx.x;
    const int tr = tid >> 4;           // 0..15
    const int tc = tid & 15;           // 0..15
    const int m0 = blockIdx.x * 128;
    const int n0 = blockIdx.y * BN;

    // global->smem load mapping
    const int a_row = tid >> 1;               // 0..127
    const int a_col = (tid & 1) * 4;          // 0 or 4
    const int b_row = tid >> 5;               // 0..7
    const int b_col = (tid & 31) * (BN / 32); // stride 4 (BN=128) or 2 (BN=64)

    float acc[8][TN];
#pragma unroll
    for (int i = 0; i < 8; i++)
#pragma unroll
        for (int j = 0; j < TN; j++) acc[i][j] = 0.f;

    const float* aP = A + (size_t)(m0 + a_row) * Kdim + a_col;
    const float* bP = Bw + (size_t)b_row * Ndim + n0 + b_col;

    for (int k0 = 0; k0 < Kdim; k0 += 8) {
        float4 a4 = *(const float4*)(aP + k0);
        As[a_col + 0][a_row] = a4.x;
        As[a_col + 1][a_row] = a4.y;
        As[a_col + 2][a_row] = a4.z;
        As[a_col + 3][a_row] = a4.w;
        if (BN == 128) {
            float4 b4 = *(const float4*)(bP + (size_t)k0 * Ndim);
            Bs[b_row][b_col + 0] = b4.x;
            Bs[b_row][b_col + 1] = b4.y;
            Bs[b_row][b_col + 2] = b4.z;
            Bs[b_row][b_col + 3] = b4.w;
        } else {
            float2 b2 = *(const float2*)(bP + (size_t)k0 * Ndim);
            Bs[b_row][b_col + 0] = b2.x;
            Bs[b_row][b_col + 1] = b2.y;
        }
        __syncthreads();

#pragma unroll
        for (int k = 0; k < 8; k++) {
            float a[8], b[TN];
            *(float4*)&a[0] = *(const float4*)&As[k][tr * 4];
            *(float4*)&a[4] = *(const float4*)&As[k][tr * 4 + 64];
            *(float4*)&b[0] = *(const float4*)&Bs[k][tc * 4];
            if (TN == 8)
                *(float4*)&b[4] = *(const float4*)&Bs[k][tc * 4 + 64];
#pragma unroll
            for (int i = 0; i < 8; i++)
#pragma unroll
                for (int j = 0; j < TN; j++) acc[i][j] += a[i] * b[j];
        }
        __syncthreads();
    }

#pragma unroll
    for (int i = 0; i < 8; i++) {
        const int m = m0 + tr * 4 + (i & 3) + (i >> 2) * 64;
#pragma unroll
        for (int jg = 0; jg < TN / 4; jg++) {
            const int n = n0 + tc * 4 + jg * 64;
            float4 r;
            r.x = acc[i][jg * 4 + 0];
            r.y = acc[i][jg * 4 + 1];
            r.z = acc[i][jg * 4 + 2];
            r.w = acc[i][jg * 4 + 3];
            if (bias) {
                r.x += bias[n + 0];
                r.y += bias[n + 1];
                r.z += bias[n + 2];
                r.w += bias[n + 3];
            }
            *(float4*)&C[(size_t)m * Ndim + n] = r;
        }
    }
}

// ---------------------------------------------------------------------------
// Flash attention as two 64x64x64 register-tile GEMMs per key tile.
// Block: one (b,h), 64 queries. 256 threads, thread grid 16x16:
//   thread (tr,tc) owns q rows tr*4..+3, key cols tc*4..+3 (S / P),
//   and q rows tr*4..+3, dim cols tc*4..+3 (O).
// Softmax row-reduce = shfl over the 16 contiguous lanes sharing tr.
// Dynamic smem: Qs,Ks (d-major) + Vs,Ps (row-major), each 64x68 floats.
// ---------------------------------------------------------------------------
#define SMP 68  // padded row stride (floats); multiple of 4 -> float4 aligned

__global__ void __launch_bounds__(256) attn64(
    const float* __restrict__ Q, const float* __restrict__ K,
    const float* __restrict__ V, float* __restrict__ O)
{
    extern __shared__ float sm[];
    float* Qs = sm;                  // [d][q]   (transposed, pre-scaled)
    float* Ks = sm + 64 * SMP;       // [d][key] (transposed)
    float* Vs = sm + 2 * 64 * SMP;   // [key][d]
    float* Ps = sm + 3 * 64 * SMP;   // [q][key]

    const int b = blockIdx.y / HEADS;
    const int h = blockIdx.y % HEADS;
    const int q0 = blockIdx.x * 64;
    const int tid = threadIdx.x;
    const int tr = tid >> 4;
    const int tc = tid & 15;

    // ---- load Q tile, transposed + pre-scaled -----------------------------
    {
        const int qi = tid & 63;
        const int dg = (tid >> 6) * 16;
        const float* qp = Q + (size_t)(b * NN + q0 + qi) * ID + h * DH + dg;
#pragma unroll
        for (int l4 = 0; l4 < 4; l4++) {
            float4 v = *(const float4*)(qp + l4 * 4);
            const int d = dg + l4 * 4;
            Qs[(d + 0) * SMP + qi] = v.x * ATT_SCALE;
            Qs[(d + 1) * SMP + qi] = v.y * ATT_SCALE;
            Qs[(d + 2) * SMP + qi] = v.z * ATT_SCALE;
            Qs[(d + 3) * SMP + qi] = v.w * ATT_SCALE;
        }
    }

    float mrow[4], lrow[4], o[4][4];
#pragma unroll
    for (int i = 0; i < 4; i++) {
        mrow[i] = -INFINITY;
        lrow[i] = 0.f;
#pragma unroll
        for (int j = 0; j < 4; j++) o[i][j] = 0.f;
    }

    for (int j0 = 0; j0 < MM; j0 += 64) {
        // ---- load K (transposed) and V (row-major) tiles ------------------
        {
            const int key = tid & 63;
            const int dg = (tid >> 6) * 16;
            const size_t base = (size_t)(b * MM + j0 + key) * ID + h * DH + dg;
#pragma unroll
            for (int l4 = 0; l4 < 4; l4++) {
                const int d = dg + l4 * 4;
                float4 kv = *(const float4*)(K + base + l4 * 4);
                Ks[(d + 0) * SMP + key] = kv.x;
                Ks[(d + 1) * SMP + key] = kv.y;
                Ks[(d + 2) * SMP + key] = kv.z;
                Ks[(d + 3) * SMP + key] = kv.w;
                float4 vv = *(const float4*)(V + base + l4 * 4);
                *(float4*)&Vs[key * SMP + d] = vv;
            }
        }
        __syncthreads();

        // ---- S = Q @ K^T (64x64x64 register-tile GEMM) --------------------
        float s[4][4];
#pragma unroll
        for (int i = 0; i < 4; i++)
#pragma unroll
            for (int j = 0; j < 4; j++) s[i][j] = 0.f;

#pragma unroll 8
        for (int d = 0; d < 64; d++) {
            float4 qa = *(const float4*)&Qs[d * SMP + tr * 4];
            float4 kb = *(const float4*)&Ks[d * SMP + tc * 4];
            const float a[4] = {qa.x, qa.y, qa.z, qa.w};
            const float bv[4] = {kb.x, kb.y, kb.z, kb.w};
#pragma unroll
            for (int i = 0; i < 4; i++)
#pragma unroll
                for (int j = 0; j < 4; j++) s[i][j] += a[i] * bv[j];
        }

        // ---- online softmax (row reduce over 16 lanes sharing tr) ---------
#pragma unroll
        for (int i = 0; i < 4; i++) {
            float tm = fmaxf(fmaxf(s[i][0], s[i][1]), fmaxf(s[i][2], s[i][3]));
            tm = fmaxf(tm, __shfl_xor_sync(0xffffffffu, tm, 1));
            tm = fmaxf(tm, __shfl_xor_sync(0xffffffffu, tm, 2));
            tm = fmaxf(tm, __shfl_xor_sync(0xffffffffu, tm, 4));
            tm = fmaxf(tm, __shfl_xor_sync(0xffffffffu, tm, 8));
            const float mn = fmaxf(mrow[i], tm);
            const float alpha = __expf(mrow[i] - mn);  // 0 when mrow == -inf
            mrow[i] = mn;
            float ls = 0.f;
#pragma unroll
            for (int j = 0; j < 4; j++) {
                s[i][j] = __expf(s[i][j] - mn);
                ls += s[i][j];
            }
            lrow[i] = lrow[i] * alpha + ls;  // lane-partial; reduced at end
#pragma unroll
            for (int j = 0; j < 4; j++) o[i][j] *= alpha;
            float4 pv = {s[i][0], s[i][1], s[i][2], s[i][3]};
            *(float4*)&Ps[(tr * 4 + i) * SMP + tc * 4] = pv;
        }
        __syncthreads();

        // ---- O += P @ V (64x64x64) ----------------------------------------
#pragma unroll 4
        for (int key = 0; key < 64; key++) {
            float4 vb = *(const float4*)&Vs[key * SMP + tc * 4];
            const float bv[4] = {vb.x, vb.y, vb.z, vb.w};
            float a0 = Ps[(tr * 4 + 0) * SMP + key];  // broadcast LDS
            float a1 = Ps[(tr * 4 + 1) * SMP + key];
            float a2 = Ps[(tr * 4 + 2) * SMP + key];
            float a3 = Ps[(tr * 4 + 3) * SMP + key];
#pragma unroll
            for (int j = 0; j < 4; j++) {
                o[0][j] += a0 * bv[j];
                o[1][j] += a1 * bv[j];
                o[2][j] += a2 * bv[j];
                o[3][j] += a3 * bv[j];
            }
        }
        __syncthreads();
    }

    // ---- finalize: reduce l across 16 lanes, normalize, store -------------
#pragma unroll
    for (int i = 0; i < 4; i++) {
        float li = lrow[i];
        li += __shfl_xor_sync(0xffffffffu, li, 1);
        li += __shfl_xor_sync(0xffffffffu, li, 2);
        li += __shfl_xor_sync(0xffffffffu, li, 4);
        li += __shfl_xor_sync(0xffffffffu, li, 8);
        const float inv = 1.f / li;
        float4 r = {o[i][0] * inv, o[i][1] * inv, o[i][2] * inv, o[i][3] * inv};
        *(float4*)&O[(size_t)(b * NN + q0 + tr * 4 + i) * ID + h * DH + tc * 4] = r;
    }
}

// ---------------------------------------------------------------------------
// Launch: x, context, Wq, Wk, Wv, Wo, bo  ->  out [B, N, QD] fp32
// ---------------------------------------------------------------------------
extern "C" void kernel_launch(void* const* d_in, const int* in_sizes, int n_in,
                              void* d_out, int out_size)
{
    (void)in_sizes; (void)n_in; (void)out_size;
    const float* x   = (const float*)d_in[0];
    const float* ctx = (const float*)d_in[1];
    const float* Wq  = (const float*)d_in[2];
    const float* Wk  = (const float*)d_in[3];
    const float* Wv  = (const float*)d_in[4];
    const float* Wo  = (const float*)d_in[5];
    const float* bo  = (const float*)d_in[6];
    float* out = (float*)d_out;

    float *qb, *kb, *vb, *ob;
    cudaGetSymbolAddress((void**)&qb, g_Q);
    cudaGetSymbolAddress((void**)&kb, g_K);
    cudaGetSymbolAddress((void**)&vb, g_V);
    cudaGetSymbolAddress((void**)&ob, g_O);

    const int attn_smem = 4 * 64 * SMP * sizeof(float);  // 69,632 B
    cudaFuncSetAttribute(attn64, cudaFuncAttributeMaxDynamicSharedMemorySize,
                         attn_smem);

    // Q = x @ Wq        : [16384,320] @ [320,512]
    gemm_tile<128, 8><<<dim3(BB * NN / 128, ID / 128), 256>>>(
        x, Wq, qb, nullptr, ID, QD);
    // K = ctx @ Wk      : [4096,768] @ [768,512]
    gemm_tile<128, 8><<<dim3(BB * MM / 128, ID / 128), 256>>>(
        ctx, Wk, kb, nullptr, ID, CD);
    // V = ctx @ Wv
    gemm_tile<128, 8><<<dim3(BB * MM / 128, ID / 128), 256>>>(
        ctx, Wv, vb, nullptr, ID, CD);
    // attention -> g_O  (b, n, h*d layout)
    attn64<<<dim3(NN / 64, BB * HEADS), 256, attn_smem>>>(qb, kb, vb, ob);
    // out = g_O @ Wo + bo : [16384,512] @ [512,320]
    gemm_tile<64, 4><<<dim3(BB * NN / 128, QD / 64), 256>>>(
        ob, Wo, out, bo, QD, ID);
}

// round 9
// speedup vs baseline: 9.9152x; 3.1606x over previous
#include <cuda_runtime.h>
#include <math.h>

// Problem constants (fixed by reference setup_inputs)
#define BB 4
#define NN 4096
#define MM 1024
#define QD 320
#define CD 768
#define ID 512
#define HEADS 8
#define DH 64
#define ATT_SCALE 0.125f  // 64^-0.5

// Scratch (static device globals -- allocation-free per harness rules)
__device__ float g_Q[(size_t)BB * NN * ID];
__device__ float g_K[(size_t)BB * MM * ID];
__device__ float g_V[(size_t)BB * MM * ID];
__device__ float g_O[(size_t)BB * NN * ID];

// ---------------------------------------------------------------------------
// tf32 helpers
// ---------------------------------------------------------------------------
__device__ __forceinline__ unsigned f2t(float f) {
    unsigned u;
    asm("cvt.rna.tf32.f32 %0, %1;" : "=r"(u) : "f"(f));
    return u;
}

// C(16x8) += A(16x8) * B(8x8), tf32 inputs, fp32 accum.
// Fragment spec (lane = g*4+t, g=lane>>2, t=lane&3):
//   A: a0=(g,t) a1=(g+8,t) a2=(g,t+4) a3=(g+8,t+4)   [row, kcol]
//   B: b0=(k=t,n=g) b1=(k=t+4,n=g)
//   C: c0=(g,2t) c1=(g,2t+1) c2=(g+8,2t) c3=(g+8,2t+1)
__device__ __forceinline__ void mma8(float* c, const unsigned* a, const unsigned* b) {
    asm volatile(
        "mma.sync.aligned.m16n8k8.row.col.f32.tf32.tf32.f32 "
        "{%0,%1,%2,%3}, {%4,%5,%6,%7}, {%8,%9}, {%0,%1,%2,%3};"
        : "+f"(c[0]), "+f"(c[1]), "+f"(c[2]), "+f"(c[3])
        : "r"(a[0]), "r"(a[1]), "r"(a[2]), "r"(a[3]), "r"(b[0]), "r"(b[1]));
}

// ---------------------------------------------------------------------------
// tf32 MMA GEMM: C[M,N] = A[M,K] @ B[K,N] (+bias)
// Block tile 128 x BN, BK=32, 256 threads = 8 warps (WR x WC).
// Natural smem layouts: As[m][k] stride 36 (banks 4g+t: conflict-free frag
// loads), Bs[k][n] stride BN+8 (banks 8t+g: conflict-free). Scalar LDS frag
// gathers straight off the fragment spec. Single buffer, prefetch in regs.
// Requires M%128==0, N%BN==0, K%32==0.
// ---------------------------------------------------------------------------
template <int BN, int WR, int WC>
__global__ void __launch_bounds__(256) gemm_mma(
    const float* __restrict__ A, const float* __restrict__ Bw,
    float* __restrict__ C, const float* __restrict__ bias,
    int Ndim, int Kdim)
{
    constexpr int MT = 128 / (WR * 16);
    constexpr int NT = BN / (WC * 8);
    constexpr int BLD = BN / 32;
    constexpr int ASTR = 36;       // 32 + 4
    constexpr int BSTR = BN + 8;

    __shared__ unsigned As[128 * ASTR];
    __shared__ unsigned Bs[32 * BSTR];

    const int tid = threadIdx.x;
    const int w = tid >> 5, lane = tid & 31;
    const int wm = w / WC, wn = w % WC;
    const int g = lane >> 2, t = lane & 3;
    const int m0 = blockIdx.x * 128, n0 = blockIdx.y * BN;

    // gmem -> reg load mapping
    int arow[4], acol[4];
#pragma unroll
    for (int i = 0; i < 4; i++) {
        const int fl = i * 256 + tid;
        arow[i] = fl >> 3;          // 0..127
        acol[i] = (fl & 7) * 4;     // 0..28
    }
    int brow[BLD], bcol[BLD];
#pragma unroll
    for (int i = 0; i < BLD; i++) {
        const int fl = i * 256 + tid;
        brow[i] = fl / (BN / 4);    // 0..31
        bcol[i] = (fl % (BN / 4)) * 4;
    }

    float acc[MT][NT][4];
#pragma unroll
    for (int mt = 0; mt < MT; mt++)
#pragma unroll
        for (int nt = 0; nt < NT; nt++)
#pragma unroll
            for (int r = 0; r < 4; r++) acc[mt][nt][r] = 0.f;

    float4 ra[4], rb[BLD];
    auto ldg = [&](int k0) {
#pragma unroll
        for (int i = 0; i < 4; i++)
            ra[i] = *(const float4*)(A + (size_t)(m0 + arow[i]) * Kdim + k0 + acol[i]);
#pragma unroll
        for (int i = 0; i < BLD; i++)
            rb[i] = *(const float4*)(Bw + (size_t)(k0 + brow[i]) * Ndim + n0 + bcol[i]);
    };
    auto sts = [&]() {
#pragma unroll
        for (int i = 0; i < 4; i++) {
            uint4 u = {f2t(ra[i].x), f2t(ra[i].y), f2t(ra[i].z), f2t(ra[i].w)};
            *(uint4*)&As[arow[i] * ASTR + acol[i]] = u;   // [m][k]
        }
#pragma unroll
        for (int i = 0; i < BLD; i++) {
            uint4 u = {f2t(rb[i].x), f2t(rb[i].y), f2t(rb[i].z), f2t(rb[i].w)};
            *(uint4*)&Bs[brow[i] * BSTR + bcol[i]] = u;   // [k][n]
        }
    };

    const int nIter = Kdim >> 5;
    ldg(0);
#pragma unroll 1
    for (int it = 0; it < nIter; it++) {
        sts();
        __syncthreads();
        if (it + 1 < nIter) ldg((it + 1) << 5);
        // compute on this tile
        const unsigned* Ab = As + (wm * MT * 16 + g) * ASTR + t;
        const unsigned* Bb = Bs + (wn * NT * 8 + g) + t * BSTR;
#pragma unroll
        for (int ks = 0; ks < 4; ks++) {
            unsigned af[MT][4], bf[NT][2];
#pragma unroll
            for (int mt = 0; mt < MT; mt++) {
                const unsigned* ap = Ab + mt * 16 * ASTR + ks * 8;
                af[mt][0] = ap[0];              // (g,       t)
                af[mt][1] = ap[8 * ASTR];       // (g+8,     t)
                af[mt][2] = ap[4];              // (g,     t+4)
                af[mt][3] = ap[8 * ASTR + 4];   // (g+8,   t+4)
            }
#pragma unroll
            for (int nt = 0; nt < NT; nt++) {
                const unsigned* bp = Bb + ks * 8 * BSTR + nt * 8;
                bf[nt][0] = bp[0];              // (k=t,   n=g)
                bf[nt][1] = bp[4 * BSTR];       // (k=t+4, n=g)
            }
#pragma unroll
            for (int mt = 0; mt < MT; mt++)
#pragma unroll
                for (int nt = 0; nt < NT; nt++)
                    mma8(acc[mt][nt], af[mt], bf[nt]);
        }
        __syncthreads();
    }

    // epilogue (C fragment spec)
#pragma unroll
    for (int mt = 0; mt < MT; mt++) {
        const int row = m0 + (wm * MT + mt) * 16 + g;
#pragma unroll
        for (int nt = 0; nt < NT; nt++) {
            const int col = n0 + (wn * NT + nt) * 8 + t * 2;
            float b0 = 0.f, b1 = 0.f;
            if (bias) { b0 = bias[col]; b1 = bias[col + 1]; }
            float2 v0 = {acc[mt][nt][0] + b0, acc[mt][nt][1] + b1};
            float2 v1 = {acc[mt][nt][2] + b0, acc[mt][nt][3] + b1};
            *(float2*)&C[(size_t)row * Ndim + col] = v0;
            *(float2*)&C[(size_t)(row + 8) * Ndim + col] = v1;
        }
    }
}

// ---------------------------------------------------------------------------
// Flash attention with tf32 MMA, natural smem layouts.
// Block: one (b,h), 64 queries. 8 warps: wm=w>>1 (16 q rows), wn=w&1.
// S phase: warp tile 16q x 32key (wn splits keys); PV: 16q x 32d (wn splits d).
// Qs[q][d] s68, Ks[key][d] s68, Vs[key][d] s72, Ps[q][key] s68 (all tf32).
// ---------------------------------------------------------------------------
#define QSTR 68
#define VSTR 72
#define ATTN_SMEM_U (3 * 64 * QSTR + 64 * VSTR + 384)

__global__ void __launch_bounds__(256) attn_mma(
    const float* __restrict__ Q, const float* __restrict__ K,
    const float* __restrict__ V, float* __restrict__ O)
{
    extern __shared__ unsigned sh[];
    unsigned* Qs = sh;                    // [64][68]
    unsigned* Ks = Qs + 64 * QSTR;        // [64][68]
    unsigned* Ps = Ks + 64 * QSTR;        // [64][68]
    unsigned* Vs = Ps + 64 * QSTR;        // [64][72]
    float* maxp = (float*)(Vs + 64 * VSTR);  // [2][64]
    float* sump = maxp + 128;                // [2][64]
    float* m_s  = sump + 128;                // [64]
    float* l_s  = m_s + 64;                  // [64]

    const int tid = threadIdx.x;
    const int w = tid >> 5, lane = tid & 31;
    const int wm = w >> 1, wn = w & 1;
    const int g = lane >> 2, t = lane & 3;
    const int b = blockIdx.y >> 3, h = blockIdx.y & 7;
    const int q0 = blockIdx.x * 64;
    const int row0 = wm * 16 + g, row1 = row0 + 8;

    if (tid < 64) { m_s[tid] = -INFINITY; l_s[tid] = 0.f; }

    // ---- load Q tile (scaled, tf32), natural [q][d] -----------------------
#pragma unroll
    for (int i = 0; i < 4; i++) {
        const int fl = i * 256 + tid;
        const int qi = fl >> 4, d4 = (fl & 15) * 4;
        const float4 v = *(const float4*)(Q + (size_t)(b * NN + q0 + qi) * ID + h * DH + d4);
        uint4 u = {f2t(v.x * ATT_SCALE), f2t(v.y * ATT_SCALE),
                   f2t(v.z * ATT_SCALE), f2t(v.w * ATT_SCALE)};
        *(uint4*)&Qs[qi * QSTR + d4] = u;
    }

    float o[4][4];
#pragma unroll
    for (int nt = 0; nt < 4; nt++)
#pragma unroll
        for (int r = 0; r < 4; r++) o[nt][r] = 0.f;

    for (int j0 = 0; j0 < MM; j0 += 64) {
        // ---- load K, V tiles, natural [key][d] ----------------------------
#pragma unroll
        for (int i = 0; i < 4; i++) {
            const int fl = i * 256 + tid;
            const int key = fl >> 4, d4 = (fl & 15) * 4;
            const size_t gb = (size_t)(b * MM + j0 + key) * ID + h * DH + d4;
            const float4 kv = *(const float4*)(K + gb);
            uint4 uk = {f2t(kv.x), f2t(kv.y), f2t(kv.z), f2t(kv.w)};
            *(uint4*)&Ks[key * QSTR + d4] = uk;
            const float4 vv = *(const float4*)(V + gb);
            uint4 uv = {f2t(vv.x), f2t(vv.y), f2t(vv.z), f2t(vv.w)};
            *(uint4*)&Vs[key * VSTR + d4] = uv;
        }
        __syncthreads();

        // ---- S = Q @ K^T : A=Q[q][d], B=K^T (k=d, n=key) ------------------
        float s[4][4];
#pragma unroll
        for (int nt = 0; nt < 4; nt++)
#pragma unroll
            for (int r = 0; r < 4; r++) s[nt][r] = 0.f;

        {
            const unsigned* Ab = Qs + (wm * 16 + g) * QSTR + t;
            const unsigned* Bb = Ks + (wn * 32 + g) * QSTR + t;
#pragma unroll
            for (int ks = 0; ks < 8; ks++) {
                unsigned af[4];
                const unsigned* ap = Ab + ks * 8;
                af[0] = ap[0];
                af[1] = ap[8 * QSTR];
                af[2] = ap[4];
                af[3] = ap[8 * QSTR + 4];
#pragma unroll
                for (int nt = 0; nt < 4; nt++) {
                    // b0 = K[key = base+g][d = ks*8+t], b1 = d+4
                    const unsigned* bp = Bb + nt * 8 * QSTR + ks * 8;
                    unsigned bf[2] = {bp[0], bp[4]};
                    mma8(s[nt], af, bf);
                }
            }
        }

        // ---- phase A: warp-local row max -> smem partials -----------------
        const float mo0 = m_s[row0], mo1 = m_s[row1];
        float tm0 = fmaxf(fmaxf(s[0][0], s[0][1]), fmaxf(s[1][0], s[1][1]));
        tm0 = fmaxf(tm0, fmaxf(fmaxf(s[2][0], s[2][1]), fmaxf(s[3][0], s[3][1])));
        float tm1 = fmaxf(fmaxf(s[0][2], s[0][3]), fmaxf(s[1][2], s[1][3]));
        tm1 = fmaxf(tm1, fmaxf(fmaxf(s[2][2], s[2][3]), fmaxf(s[3][2], s[3][3])));
        tm0 = fmaxf(tm0, __shfl_xor_sync(0xffffffffu, tm0, 1));
        tm0 = fmaxf(tm0, __shfl_xor_sync(0xffffffffu, tm0, 2));
        tm1 = fmaxf(tm1, __shfl_xor_sync(0xffffffffu, tm1, 1));
        tm1 = fmaxf(tm1, __shfl_xor_sync(0xffffffffu, tm1, 2));
        if (t == 0) {
            maxp[wn * 64 + row0] = tm0;
            maxp[wn * 64 + row1] = tm1;
        }
        __syncthreads();

        // ---- phase B: exp, sums, P -> smem natural [q][key], O rescale ----
        const float M0 = fmaxf(mo0, fmaxf(maxp[row0], maxp[64 + row0]));
        const float M1 = fmaxf(mo1, fmaxf(maxp[row1], maxp[64 + row1]));
        const float al0 = __expf(mo0 - M0);
        const float al1 = __expf(mo1 - M1);
        float sum0 = 0.f, sum1 = 0.f;
#pragma unroll
        for (int nt = 0; nt < 4; nt++) {
            s[nt][0] = __expf(s[nt][0] - M0);
            s[nt][1] = __expf(s[nt][1] - M0);
            s[nt][2] = __expf(s[nt][2] - M1);
            s[nt][3] = __expf(s[nt][3] - M1);
            sum0 += s[nt][0] + s[nt][1];
            sum1 += s[nt][2] + s[nt][3];
        }
        sum0 += __shfl_xor_sync(0xffffffffu, sum0, 1);
        sum0 += __shfl_xor_sync(0xffffffffu, sum0, 2);
        sum1 += __shfl_xor_sync(0xffffffffu, sum1, 1);
        sum1 += __shfl_xor_sync(0xffffffffu, sum1, 2);
        if (t == 0) {
            sump[wn * 64 + row0] = sum0;
            sump[wn * 64 + row1] = sum1;
            if (wn == 0) { m_s[row0] = M0; m_s[row1] = M1; }
        }
        // P store: C-frag (row0/row1, col = wn*32 + nt*8 + 2t{,+1})
#pragma unroll
        for (int nt = 0; nt < 4; nt++) {
            const int col = wn * 32 + nt * 8 + t * 2;
            Ps[row0 * QSTR + col]     = f2t(s[nt][0]);
            Ps[row0 * QSTR + col + 1] = f2t(s[nt][1]);
            Ps[row1 * QSTR + col]     = f2t(s[nt][2]);
            Ps[row1 * QSTR + col + 1] = f2t(s[nt][3]);
        }
#pragma unroll
        for (int nt = 0; nt < 4; nt++) {
            o[nt][0] *= al0; o[nt][1] *= al0;
            o[nt][2] *= al1; o[nt][3] *= al1;
        }
        __syncthreads();

        // ---- phase C: l update + O += P @ V -------------------------------
        if (wn == 0 && t == 0) {
            l_s[row0] = l_s[row0] * al0 + sump[row0] + sump[64 + row0];
            l_s[row1] = l_s[row1] * al1 + sump[row1] + sump[64 + row1];
        }
        {
            const unsigned* Ab = Ps + (wm * 16 + g) * QSTR + t;
            const unsigned* Bb = Vs + wn * 32 + g + t * VSTR;
#pragma unroll
            for (int ks = 0; ks < 8; ks++) {
                unsigned af[4];
                const unsigned* ap = Ab + ks * 8;
                af[0] = ap[0];
                af[1] = ap[8 * QSTR];
                af[2] = ap[4];
                af[3] = ap[8 * QSTR + 4];
#pragma unroll
                for (int nt = 0; nt < 4; nt++) {
                    // b0 = V[key = ks*8+t][d = wn*32 + nt*8 + g], b1 = key+4
                    const unsigned* bp = Bb + ks * 8 * VSTR + nt * 8;
                    unsigned bf[2] = {bp[0], bp[4 * VSTR]};
                    mma8(o[nt], af, bf);
                }
            }
        }
        __syncthreads();
    }

    // ---- finalize ---------------------------------------------------------
    const float inv0 = 1.f / l_s[row0];
    const float inv1 = 1.f / l_s[row1];
#pragma unroll
    for (int nt = 0; nt < 4; nt++) {
        const int d = wn * 32 + nt * 8 + t * 2;
        float2 v0 = {o[nt][0] * inv0, o[nt][1] * inv0};
        float2 v1 = {o[nt][2] * inv1, o[nt][3] * inv1};
        *(float2*)&O[(size_t)(b * NN + q0 + row0) * ID + h * DH + d] = v0;
        *(float2*)&O[(size_t)(b * NN + q0 + row1) * ID + h * DH + d] = v1;
    }
}

// ---------------------------------------------------------------------------
// Launch: x, context, Wq, Wk, Wv, Wo, bo  ->  out [B, N, QD] fp32
// ---------------------------------------------------------------------------
extern "C" void kernel_launch(void* const* d_in, const int* in_sizes, int n_in,
                              void* d_out, int out_size)
{
    (void)in_sizes; (void)n_in; (void)out_size;
    const float* x   = (const float*)d_in[0];
    const float* ctx = (const float*)d_in[1];
    const float* Wq  = (const float*)d_in[2];
    const float* Wk  = (const float*)d_in[3];
    const float* Wv  = (const float*)d_in[4];
    const float* Wo  = (const float*)d_in[5];
    const float* bo  = (const float*)d_in[6];
    float* out = (float*)d_out;

    float *qb, *kb, *vb, *ob;
    cudaGetSymbolAddress((void**)&qb, g_Q);
    cudaGetSymbolAddress((void**)&kb, g_K);
    cudaGetSymbolAddress((void**)&vb, g_V);
    cudaGetSymbolAddress((void**)&ob, g_O);

    const int smem_attn = ATTN_SMEM_U * 4;  // 72,192 B
    cudaFuncSetAttribute(attn_mma,
                         cudaFuncAttributeMaxDynamicSharedMemorySize, smem_attn);

    // Q = x @ Wq        : [16384,320] @ [320,512]
    gemm_mma<128, 2, 4><<<dim3(BB * NN / 128, ID / 128), 256>>>(
        x, Wq, qb, nullptr, ID, QD);
    // K = ctx @ Wk      : [4096,768] @ [768,512]
    gemm_mma<128, 2, 4><<<dim3(BB * MM / 128, ID / 128), 256>>>(
        ctx, Wk, kb, nullptr, ID, CD);
    // V = ctx @ Wv
    gemm_mma<128, 2, 4><<<dim3(BB * MM / 128, ID / 128), 256>>>(
        ctx, Wv, vb, nullptr, ID, CD);
    // attention -> g_O  (b, n, h*d layout)
    attn_mma<<<dim3(NN / 64, BB * HEADS), 256, smem_attn>>>(qb, kb, vb, ob);
    // out = g_O @ Wo + bo : [16384,512] @ [512,320]
    gemm_mma<64, 4, 2><<<dim3(BB * NN / 128, QD / 64), 256>>>(
        ob, Wo, out, bo, QD, ID);
}